// round 14
// baseline (speedup 1.0000x reference)
#include <cuda_runtime.h>
#include <math.h>

#define R2F 0.70710678118654752440f
#define PI_F 3.14159265358979f
#define LSTR 580   /* padded per-line smem stride in float2 units */
#define F1S  264   /* g_F1 row stride in float2; columns 0..256 are valid */

typedef unsigned long long ull;

/* Blackwell packed f32x2 FMA: d = a*b + c on two packed lanes */
#define FFMA2(d,a,b,c) asm("fma.rn.f32x2 %0, %1, %2, %3;" : "=l"(d) : "l"(a), "l"(b), "l"(c))
#define PACK2(d,s)     asm("mov.b64 %0, {%1, %1};" : "=l"(d) : "r"(__float_as_uint(s)))
#define UNPACK2(lo,hi,s) asm("mov.b64 {%0, %1}, %2;" : "=f"(lo), "=f"(hi) : "l"(s))

/* ------------- static device scratch (zero-init, never allocated) --------- */
static __device__ float2 g_F1[16 * 256 * F1S];   /* row FFT, k = 0..256       */
static __device__ float2 g_A [16 * 257 * 512];   /* A[b][k<=256][h<=263 used] */
static __device__ float  g_Pf[257 * 512 * 16];   /* folded pseudo [h][w][b]   */
static __device__ float  g_c256[512 * 16];       /* w=256 column, all h, *sc  */
static __device__ float  g_part[46 * 9 * 64];    /* [grp][spl][sgn*32+q*16+b] */

__device__ __forceinline__ int padi(int i) { return i + (i >> 3); }

/* ------------- radix-8 FFT building blocks -------------------------------- */
template<int SGN>
__device__ __forceinline__ void fft8(float2 v[8]) {
    const float S = (float)SGN;
    float2 t;
#define BF(a,b) t=v[a]; v[a].x=t.x+v[b].x; v[a].y=t.y+v[b].y; v[b].x=t.x-v[b].x; v[b].y=t.y-v[b].y;
    BF(0,4) BF(1,5) BF(2,6) BF(3,7)
    { float2 a=v[5]; v[5]=make_float2(R2F*(a.x - S*a.y), R2F*(S*a.x + a.y)); }
    { float2 a=v[6]; v[6]=make_float2(-S*a.y, S*a.x); }
    { float2 a=v[7]; v[7]=make_float2(R2F*(-a.x - S*a.y), R2F*(S*a.x - a.y)); }
    BF(0,2) BF(1,3) BF(4,6) BF(5,7)
    { float2 a=v[3]; v[3]=make_float2(-S*a.y, S*a.x); }
    { float2 a=v[7]; v[7]=make_float2(-S*a.y, S*a.x); }
    BF(0,1) BF(2,3) BF(4,5) BF(6,7)
#undef BF
}

template<int SGN, int NS>
__device__ __forceinline__ void twiddle(float2 v[8], int j) {
    if (NS == 1) return;
    float base = (float)SGN * (6.283185307179586f / (float)(8 * NS)) * (float)(j & (NS - 1));
#pragma unroll
    for (int r = 1; r < 8; ++r) {
        float s, c; __sincosf(base * (float)r, &s, &c);
        float2 a = v[r];
        v[r] = make_float2(a.x * c - a.y * s, a.x * s + a.y * c);
    }
}

template<int NS>
__device__ __forceinline__ void store_stage(float2* dst, float2 v[8], int j) {
    int jd = ((j & ~(NS - 1)) << 3) + (j & (NS - 1));
    dst[padi(jd)]          = v[0];
    dst[padi(jd + NS)]     = v[4];
    dst[padi(jd + 2 * NS)] = v[2];
    dst[padi(jd + 3 * NS)] = v[6];
    dst[padi(jd + 4 * NS)] = v[1];
    dst[padi(jd + 5 * NS)] = v[5];
    dst[padi(jd + 6 * NS)] = v[3];
    dst[padi(jd + 7 * NS)] = v[7];
}

__device__ __forceinline__ void load_stage(const float2* src, float2 v[8], int j) {
#pragma unroll
    for (int r = 0; r < 8; ++r) v[r] = src[padi(j + 64 * r)];
}

/* ---- pass 1: packed row FFT, two real rows per complex transform --------- */
__global__ __launch_bounds__(256) void k_fft_rows_fwd(const float* __restrict__ x) {
    __shared__ float2 sb[2][4][LSTR];
    int bid = blockIdx.x, b = bid >> 5, h0 = (bid & 31) << 3;
    int tid = threadIdx.x, line = tid >> 6, j = tid & 63;
    float2 v[8];
    const float* xa = x + (size_t)(b * 256 + h0 + 2 * line) * 256;
    const float* xb = xa + 256;
#pragma unroll
    for (int r = 0; r < 8; ++r)
        v[r] = (r < 4) ? make_float2(xa[j + 64 * r], xb[j + 64 * r])
                       : make_float2(0.f, 0.f);
    fft8<-1>(v);
    store_stage<1>(&sb[0][line][0], v, j);
    __syncthreads();
    load_stage(&sb[0][line][0], v, j);
    twiddle<-1, 8>(v, j); fft8<-1>(v);
    store_stage<8>(&sb[1][line][0], v, j);
    __syncthreads();
    load_stage(&sb[1][line][0], v, j);
    twiddle<-1, 64>(v, j); fft8<-1>(v);
    __syncthreads();
    sb[0][line][padi(j)]       = v[0];
    sb[0][line][padi(j + 64)]  = v[4];
    sb[0][line][padi(j + 128)] = v[2];
    sb[0][line][padi(j + 192)] = v[6];
    sb[0][line][padi(j + 256)] = v[1];
    sb[0][line][padi(j + 320)] = v[5];
    sb[0][line][padi(j + 384)] = v[3];
    sb[0][line][padi(j + 448)] = v[7];
    __syncthreads();
#pragma unroll
    for (int it = 0; it < 5; ++it) {
        int idx = it * 256 + tid;
        int ln = idx & 3, k = idx >> 2;
        if (k <= 256) {
            float2 Z  = sb[0][ln][padi(k)];
            float2 Zm = sb[0][ln][padi((512 - k) & 511)];
            float2 Fa = make_float2((Z.x + Zm.x) * 0.5f, (Z.y - Zm.y) * 0.5f);
            float2 Fb = make_float2((Z.y + Zm.y) * 0.5f, (Zm.x - Z.x) * 0.5f);
            g_F1[(size_t)(b * 256 + h0 + 2 * ln) * F1S + k]     = Fa;
            g_F1[(size_t)(b * 256 + h0 + 2 * ln + 1) * F1S + k] = Fb;
        }
    }
}

/* ---- pass 2+3 fused: fwd FFT over h, magnitude, inverse FFT over l ------- */
__global__ __launch_bounds__(256) void k_fft_cols_absinv() {
    __shared__ float2 sb[2][4][LSTR];
    int bid = blockIdx.x, b = bid / 65, cg = bid % 65, kcb = cg << 2;
    int tid = threadIdx.x, line = tid >> 6, j = tid & 63;
#pragma unroll
    for (int k = 0; k < 8; ++k) {
        int idx = tid + 256 * k, l4 = idx & 3, i = idx >> 2;
        int kc = kcb + l4;
        float2 val = (i < 256 && kc <= 256)
                   ? g_F1[(size_t)(b * 256 + i) * F1S + kc] : make_float2(0.f, 0.f);
        sb[0][l4][padi(i)] = val;
    }
    __syncthreads();
    float2 v[8];
    load_stage(&sb[0][line][0], v, j);
    fft8<-1>(v);
    store_stage<1>(&sb[1][line][0], v, j);
    __syncthreads();
    load_stage(&sb[1][line][0], v, j);
    twiddle<-1, 8>(v, j); fft8<-1>(v);
    store_stage<8>(&sb[0][line][0], v, j);
    __syncthreads();
    load_stage(&sb[0][line][0], v, j);
    twiddle<-1, 64>(v, j); fft8<-1>(v);
    __syncthreads();
    sb[1][line][padi(j)]       = make_float2(sqrtf(v[0].x*v[0].x + v[0].y*v[0].y), 0.f);
    sb[1][line][padi(j + 64)]  = make_float2(sqrtf(v[4].x*v[4].x + v[4].y*v[4].y), 0.f);
    sb[1][line][padi(j + 128)] = make_float2(sqrtf(v[2].x*v[2].x + v[2].y*v[2].y), 0.f);
    sb[1][line][padi(j + 192)] = make_float2(sqrtf(v[6].x*v[6].x + v[6].y*v[6].y), 0.f);
    sb[1][line][padi(j + 256)] = make_float2(sqrtf(v[1].x*v[1].x + v[1].y*v[1].y), 0.f);
    sb[1][line][padi(j + 320)] = make_float2(sqrtf(v[5].x*v[5].x + v[5].y*v[5].y), 0.f);
    sb[1][line][padi(j + 384)] = make_float2(sqrtf(v[3].x*v[3].x + v[3].y*v[3].y), 0.f);
    sb[1][line][padi(j + 448)] = make_float2(sqrtf(v[7].x*v[7].x + v[7].y*v[7].y), 0.f);
    __syncthreads();
    load_stage(&sb[1][line][0], v, j);
    fft8<1>(v);
    store_stage<1>(&sb[0][line][0], v, j);
    __syncthreads();
    load_stage(&sb[0][line][0], v, j);
    twiddle<1, 8>(v, j); fft8<1>(v);
    store_stage<8>(&sb[1][line][0], v, j);
    __syncthreads();
    load_stage(&sb[1][line][0], v, j);
    twiddle<1, 64>(v, j); fft8<1>(v);
    int kr = kcb + line;
    if (kr <= 256) {
        float2* o = g_A + (size_t)(b * 257 + kr) * 512;
        o[j] = v[0]; o[j + 64] = v[4]; o[j + 128] = v[2]; o[j + 192] = v[6];
        if (j < 8) o[j + 256] = v[1];   /* pass 4 reads only h <= 263 */
    }
}

/* ---- pass 4: packed inverse FFT over k, fused fold-transpose epilogue ---- */
__global__ __launch_bounds__(256) void k_fft_cols_inv() {
    __shared__ float2 sb[2][4][LSTR];
    int bid = blockIdx.x, b = bid / 33, g = bid % 33, h0 = g << 3;
    int tid = threadIdx.x, line = tid >> 6, j = tid & 63;
#pragma unroll
    for (int it = 0; it < 8; ++it) {
        int idx = it * 256 + tid, u = idx & 3, kk = idx >> 2;
        float2 sv;
        if (kk <= 256) {
            const float4 q4 = *reinterpret_cast<const float4*>(
                g_A + (size_t)(b * 257 + kk) * 512 + h0 + 2 * u);
            sv = make_float2(q4.x - q4.w, q4.y + q4.z);
        } else {
            int k2 = 512 - kk;
            const float4 q4 = *reinterpret_cast<const float4*>(
                g_A + (size_t)(b * 257 + k2) * 512 + h0 + 2 * u);
            sv = make_float2(q4.x + q4.w, q4.z - q4.y);
        }
        sb[0][u][padi(kk)] = sv;
    }
    __syncthreads();
    float2 v[8];
    load_stage(&sb[0][line][0], v, j);
    fft8<1>(v);
    store_stage<1>(&sb[1][line][0], v, j);
    __syncthreads();
    load_stage(&sb[1][line][0], v, j);
    twiddle<1, 8>(v, j); fft8<1>(v);
    store_stage<8>(&sb[0][line][0], v, j);
    __syncthreads();
    load_stage(&sb[0][line][0], v, j);
    twiddle<1, 64>(v, j); fft8<1>(v);

    const float sc = 1.f / 262144.f;
    int ha = h0 + 2 * line, hb = ha + 1;
    float wa = ((ha != 0) && (ha != 256)) ? 2.f * sc : sc;
    float wb = 2.f * sc;   /* odd hb is never 0 or 256 */
    const int perm[8] = {0, 4, 2, 6, 1, 5, 3, 7};
#pragma unroll
    for (int r = 0; r < 8; ++r) {
        int w = j + 64 * r;
        float2 pv = v[perm[r]];
        float halfw = (w == 0) ? 0.5f : 1.f;
        if (ha <= 256)
            g_Pf[((size_t)ha * 512 + w) * 16 + b] = pv.x * (wa * halfw);
        if (hb <= 256)
            g_Pf[((size_t)hb * 512 + w) * 16 + b] = pv.y * (wb * halfw);
    }
    if (j == 0) {
        float2 pv = v[1];   /* natural position w = 256 */
        if (ha <= 256) {
            g_c256[ha * 16 + b] = pv.x * sc;
            if (ha >= 1 && ha <= 255) g_c256[(512 - ha) * 16 + b] = pv.x * sc;
        }
        if (hb <= 256) {
            g_c256[hb * 16 + b] = pv.y * sc;
            if (hb <= 255) g_c256[(512 - hb) * 16 + b] = pv.y * sc;
        }
    }
}

/* ---- mask evaluator: polynomial sin(pi r) + rational closed form --------- */
struct MaskC { float Ac, Bc, Cc, s0, l1, l2; };
__device__ __forceinline__ float mask_eval(float x, const MaskC& C) {
    float u = x * x;
    float num = fmaf(fmaf(C.Ac, u, C.Bc), u, C.Cc);
    float den = x * ((u - 1.f) * (u - 4.f));
    int ki = __float2int_rn(x);
    float r = x - (float)ki;
    float r2 = r * r;
    float sv = fmaf(fmaf(fmaf(fmaf(0.0821458866f, r2, -0.599264529f),
                              r2, 2.55016403f), r2, -5.16771278f), r2, 3.14159265f) * r;
    sv = (ki & 1) ? -sv : sv;
    float m = __fdividef(sv * num, PI_F * den);
    if (den == 0.f) {
        float ax = fabsf(x);
        m = (ax == 0.f) ? C.s0 : ((ax == 1.f) ? C.l1 : C.l2);
    }
    return m;
}

/* ---- fused mask generation + contraction: 2 base thetas per block -------- */
/* grid (46, 9): spl 0..7 = 32 h-rows each; spl 8 = tail (h=256 row + w=256). */
/* Accumulators halved vs r13 (32 ull) so 2 blocks/SM fit -> 2x occupancy.   */
__global__ __launch_bounds__(256, 2) void k_contract(const float* __restrict__ lp) {
    const int grp = blockIdx.x, spl = blockIdx.y, tid = threadIdx.x;
    const float lp0 = __ldg(lp), lp1 = __ldg(lp + 1), lp2 = __ldg(lp + 2);
    MaskC C;
    C.Ac = 2.f * (lp0 - lp1 + lp2);
    C.Bc = 2.f * (-5.f * lp0 + 4.f * lp1 - lp2);
    C.Cc = 8.f * lp0;
    C.s0 = 2.f * lp0; C.l1 = lp1; C.l2 = lp2;

    float ct[2], st_[2];
#pragma unroll
    for (int q = 0; q < 2; ++q) {
        float th = (float)((double)(grp * 2 + q) * 0.017453292519943295);
        ct[q] = cosf(th);
        st_[q] = sinf(th);
    }

    float accp[32], accm[32];

    if (spl < 8) {
        ull ap2[16], am2[16];
#pragma unroll
        for (int i = 0; i < 16; ++i) { ap2[i] = 0ull; am2[i] = 0ull; }

        const int h0 = spl * 32;
#pragma unroll 1
        for (int it = 0; it < 32; ++it) {
            int idx = it * 256 + tid;
            int hi = idx >> 8, wp = idx & 255;
            float mf = (float)(h0 + hi);
            float nf = (float)wp;
            int wB = (512 - wp) & 511;

            const ulonglong2* pa = reinterpret_cast<const ulonglong2*>(
                g_Pf + (((size_t)(h0 + hi) * 512 + wp) << 4));
            const ulonglong2* pb = reinterpret_cast<const ulonglong2*>(
                g_Pf + (((size_t)(h0 + hi) * 512 + wB) << 4));

            ull Mp2[2], Mm2[2];
#pragma unroll
            for (int q = 0; q < 2; ++q) {
                float Mp = mask_eval(fmaf(mf, ct[q],  nf * st_[q]), C);
                float Mm = mask_eval(fmaf(mf, ct[q], -nf * st_[q]), C);
                PACK2(Mp2[q], Mp);
                PACK2(Mm2[q], Mm);
            }
            /* chunked: 4 x ulonglong2 (16B) per stream, low live-register set */
#pragma unroll
            for (int c = 0; c < 4; ++c) {
                ulonglong2 av = pa[c], bv = pb[c];
#pragma unroll
                for (int q = 0; q < 2; ++q) {
                    ull t;
                    int i0 = q * 8 + c * 2;
                    FFMA2(t, Mm2[q], bv.x, ap2[i0]);
                    FFMA2(ap2[i0], Mp2[q], av.x, t);
                    FFMA2(t, Mp2[q], bv.x, am2[i0]);
                    FFMA2(am2[i0], Mm2[q], av.x, t);
                    FFMA2(t, Mm2[q], bv.y, ap2[i0 + 1]);
                    FFMA2(ap2[i0 + 1], Mp2[q], av.y, t);
                    FFMA2(t, Mp2[q], bv.y, am2[i0 + 1]);
                    FFMA2(am2[i0 + 1], Mm2[q], av.y, t);
                }
            }
        }
#pragma unroll
        for (int i = 0; i < 16; ++i) {
            UNPACK2(accp[2 * i], accp[2 * i + 1], ap2[i]);
            UNPACK2(accm[2 * i], accm[2 * i + 1], am2[i]);
        }
    } else {
#pragma unroll
        for (int i = 0; i < 32; ++i) { accp[i] = 0.f; accm[i] = 0.f; }
        /* (a) row h = 256, paired over w' = 0..255 */
        {
            int wp = tid;
            float mf = -256.f, nf = (float)wp;
            int wB = (512 - wp) & 511;
            const float4* pa4 = reinterpret_cast<const float4*>(
                g_Pf + (((size_t)256 * 512 + wp) << 4));
            const float4* pb4 = reinterpret_cast<const float4*>(
                g_Pf + (((size_t)256 * 512 + wB) << 4));
            float4 a0 = pa4[0], a1 = pa4[1], a2 = pa4[2], a3 = pa4[3];
            float4 b0 = pb4[0], b1 = pb4[1], b2 = pb4[2], b3 = pb4[3];
            float pA[16] = {a0.x,a0.y,a0.z,a0.w, a1.x,a1.y,a1.z,a1.w,
                            a2.x,a2.y,a2.z,a2.w, a3.x,a3.y,a3.z,a3.w};
            float pB[16] = {b0.x,b0.y,b0.z,b0.w, b1.x,b1.y,b1.z,b1.w,
                            b2.x,b2.y,b2.z,b2.w, b3.x,b3.y,b3.z,b3.w};
#pragma unroll
            for (int q = 0; q < 2; ++q) {
                float Mp = mask_eval(fmaf(mf, ct[q],  nf * st_[q]), C);
                float Mm = mask_eval(fmaf(mf, ct[q], -nf * st_[q]), C);
#pragma unroll
                for (int b = 0; b < 16; ++b) {
                    accp[q * 16 + b] = fmaf(Mp, pA[b], fmaf(Mm, pB[b], accp[q * 16 + b]));
                    accm[q * 16 + b] = fmaf(Mm, pA[b], fmaf(Mp, pB[b], accm[q * 16 + b]));
                }
            }
        }
        /* (b) column w = 256, all h = 0..511, exact and unpaired */
#pragma unroll 1
        for (int it = 0; it < 2; ++it) {
            int h = it * 256 + tid;
            float mf = (float)(h - ((h >= 256) ? 512 : 0));
            float nf = -256.f;
            const float4* pc4 = reinterpret_cast<const float4*>(g_c256 + h * 16);
            float4 c0 = pc4[0], c1 = pc4[1], c2 = pc4[2], c3 = pc4[3];
            float P[16] = {c0.x,c0.y,c0.z,c0.w, c1.x,c1.y,c1.z,c1.w,
                           c2.x,c2.y,c2.z,c2.w, c3.x,c3.y,c3.z,c3.w};
#pragma unroll
            for (int q = 0; q < 2; ++q) {
                float Mp = mask_eval(fmaf( mf, ct[q], nf * st_[q]), C);   /* theta t */
                float Mm = mask_eval(fmaf(-mf, ct[q], nf * st_[q]), C);   /* theta 180-t */
#pragma unroll
                for (int b = 0; b < 16; ++b) {
                    accp[q * 16 + b] = fmaf(Mp, P[b], accp[q * 16 + b]);
                    accm[q * 16 + b] = fmaf(Mm, P[b], accm[q * 16 + b]);
                }
            }
        }
    }

    /* deterministic block reduction: warp shuffles, then one smem pass */
#pragma unroll
    for (int i = 0; i < 32; ++i) {
#pragma unroll
        for (int off = 16; off > 0; off >>= 1) {
            accp[i] += __shfl_down_sync(0xffffffffu, accp[i], off);
            accm[i] += __shfl_down_sync(0xffffffffu, accm[i], off);
        }
    }
    __shared__ float red[8][64];
    int wid = tid >> 5, lid = tid & 31;
    if (lid == 0) {
#pragma unroll
        for (int i = 0; i < 32; ++i) {
            red[wid][i] = accp[i];
            red[wid][32 + i] = accm[i];
        }
    }
    __syncthreads();
    if (tid < 64) {
        float s = 0.f;
#pragma unroll
        for (int w8 = 0; w8 < 8; ++w8) s += red[w8][tid];
        g_part[((size_t)grp * 9 + spl) * 64 + tid] = s;
    }
}

/* ---- final reduction: slot map (grp,q,sign) -> t, fold 1/(H*W) ----------- */
__global__ __launch_bounds__(256) void k_reduce(float* __restrict__ out) {
    int i = blockIdx.x * 256 + threadIdx.x;
    if (i >= 2880) return;
    int t = i % 180, b = i / 180;
    int bt, sign;
    if (t <= 90) { bt = t; sign = 0; }
    else         { bt = 180 - t; sign = 1; }
    int grp = bt >> 1, q = bt & 1;
    int off = sign * 32 + q * 16 + b;
    float s = 0.f;
#pragma unroll
    for (int spl = 0; spl < 9; ++spl)
        s += g_part[((size_t)grp * 9 + spl) * 64 + off];
    out[b * 180 + t] = s * (1.f / 262144.f);
}

/* -------------------------------------------------------------------------- */
extern "C" void kernel_launch(void* const* d_in, const int* in_sizes, int n_in,
                              void* d_out, int out_size) {
    const float* batch = (const float*)d_in[0];   /* [16,256,256] */
    const float* lp    = (const float*)d_in[1];   /* [3]          */
    float* out         = (float*)d_out;           /* [16,180]     */
    (void)in_sizes; (void)n_in; (void)out_size;

    k_fft_rows_fwd<<<512, 256>>>(batch);
    k_fft_cols_absinv<<<1040, 256>>>();
    k_fft_cols_inv<<<528, 256>>>();
    k_contract<<<dim3(46, 9), 256>>>(lp);
    k_reduce<<<12, 256>>>(out);
}

// round 15
// speedup vs baseline: 1.1310x; 1.1310x over previous
#include <cuda_runtime.h>
#include <math.h>

#define R2F 0.70710678118654752440f
#define PI_F 3.14159265358979f
#define LSTR 580   /* padded per-line smem stride in float2 units */
#define F1S  264   /* g_F1 row stride in float2; columns 0..256 are valid */

typedef unsigned long long ull;

/* Blackwell packed f32x2 FMA: d = a*b + c on two packed lanes */
#define FFMA2(d,a,b,c) asm("fma.rn.f32x2 %0, %1, %2, %3;" : "=l"(d) : "l"(a), "l"(b), "l"(c))
#define PACK2(d,s)     asm("mov.b64 %0, {%1, %1};" : "=l"(d) : "r"(__float_as_uint(s)))
#define UNPACK2(lo,hi,s) asm("mov.b64 {%0, %1}, %2;" : "=f"(lo), "=f"(hi) : "l"(s))

/* ------------- static device scratch (zero-init, never allocated) --------- */
static __device__ float2 g_F1[16 * 256 * F1S];   /* row FFT, k = 0..256       */
static __device__ float2 g_A [16 * 257 * 512];   /* A[b][k<=256][h<=263 used] */
static __device__ float  g_Pf[257 * 512 * 16];   /* folded pseudo [h][w][b]   */
static __device__ float  g_c256[512 * 16];       /* w=256 column, all h, *sc  */
static __device__ float  g_part[23 * 9 * 2 * 64];/* [grp][spl][bh][sgn*32+q*8+bb] */

__device__ __forceinline__ int padi(int i) { return i + (i >> 3); }

/* ------------- radix-8 FFT building blocks -------------------------------- */
template<int SGN>
__device__ __forceinline__ void fft8(float2 v[8]) {
    const float S = (float)SGN;
    float2 t;
#define BF(a,b) t=v[a]; v[a].x=t.x+v[b].x; v[a].y=t.y+v[b].y; v[b].x=t.x-v[b].x; v[b].y=t.y-v[b].y;
    BF(0,4) BF(1,5) BF(2,6) BF(3,7)
    { float2 a=v[5]; v[5]=make_float2(R2F*(a.x - S*a.y), R2F*(S*a.x + a.y)); }
    { float2 a=v[6]; v[6]=make_float2(-S*a.y, S*a.x); }
    { float2 a=v[7]; v[7]=make_float2(R2F*(-a.x - S*a.y), R2F*(S*a.x - a.y)); }
    BF(0,2) BF(1,3) BF(4,6) BF(5,7)
    { float2 a=v[3]; v[3]=make_float2(-S*a.y, S*a.x); }
    { float2 a=v[7]; v[7]=make_float2(-S*a.y, S*a.x); }
    BF(0,1) BF(2,3) BF(4,5) BF(6,7)
#undef BF
}

template<int SGN, int NS>
__device__ __forceinline__ void twiddle(float2 v[8], int j) {
    if (NS == 1) return;
    float base = (float)SGN * (6.283185307179586f / (float)(8 * NS)) * (float)(j & (NS - 1));
#pragma unroll
    for (int r = 1; r < 8; ++r) {
        float s, c; __sincosf(base * (float)r, &s, &c);
        float2 a = v[r];
        v[r] = make_float2(a.x * c - a.y * s, a.x * s + a.y * c);
    }
}

template<int NS>
__device__ __forceinline__ void store_stage(float2* dst, float2 v[8], int j) {
    int jd = ((j & ~(NS - 1)) << 3) + (j & (NS - 1));
    dst[padi(jd)]          = v[0];
    dst[padi(jd + NS)]     = v[4];
    dst[padi(jd + 2 * NS)] = v[2];
    dst[padi(jd + 3 * NS)] = v[6];
    dst[padi(jd + 4 * NS)] = v[1];
    dst[padi(jd + 5 * NS)] = v[5];
    dst[padi(jd + 6 * NS)] = v[3];
    dst[padi(jd + 7 * NS)] = v[7];
}

__device__ __forceinline__ void load_stage(const float2* src, float2 v[8], int j) {
#pragma unroll
    for (int r = 0; r < 8; ++r) v[r] = src[padi(j + 64 * r)];
}

/* ---- pass 1: packed row FFT, two real rows per complex transform --------- */
__global__ __launch_bounds__(256) void k_fft_rows_fwd(const float* __restrict__ x) {
    __shared__ float2 sb[2][4][LSTR];
    int bid = blockIdx.x, b = bid >> 5, h0 = (bid & 31) << 3;
    int tid = threadIdx.x, line = tid >> 6, j = tid & 63;
    float2 v[8];
    const float* xa = x + (size_t)(b * 256 + h0 + 2 * line) * 256;
    const float* xb = xa + 256;
#pragma unroll
    for (int r = 0; r < 8; ++r)
        v[r] = (r < 4) ? make_float2(xa[j + 64 * r], xb[j + 64 * r])
                       : make_float2(0.f, 0.f);
    fft8<-1>(v);
    store_stage<1>(&sb[0][line][0], v, j);
    __syncthreads();
    load_stage(&sb[0][line][0], v, j);
    twiddle<-1, 8>(v, j); fft8<-1>(v);
    store_stage<8>(&sb[1][line][0], v, j);
    __syncthreads();
    load_stage(&sb[1][line][0], v, j);
    twiddle<-1, 64>(v, j); fft8<-1>(v);
    __syncthreads();
    sb[0][line][padi(j)]       = v[0];
    sb[0][line][padi(j + 64)]  = v[4];
    sb[0][line][padi(j + 128)] = v[2];
    sb[0][line][padi(j + 192)] = v[6];
    sb[0][line][padi(j + 256)] = v[1];
    sb[0][line][padi(j + 320)] = v[5];
    sb[0][line][padi(j + 384)] = v[3];
    sb[0][line][padi(j + 448)] = v[7];
    __syncthreads();
#pragma unroll
    for (int it = 0; it < 5; ++it) {
        int idx = it * 256 + tid;
        int ln = idx & 3, k = idx >> 2;
        if (k <= 256) {
            float2 Z  = sb[0][ln][padi(k)];
            float2 Zm = sb[0][ln][padi((512 - k) & 511)];
            float2 Fa = make_float2((Z.x + Zm.x) * 0.5f, (Z.y - Zm.y) * 0.5f);
            float2 Fb = make_float2((Z.y + Zm.y) * 0.5f, (Zm.x - Z.x) * 0.5f);
            g_F1[(size_t)(b * 256 + h0 + 2 * ln) * F1S + k]     = Fa;
            g_F1[(size_t)(b * 256 + h0 + 2 * ln + 1) * F1S + k] = Fb;
        }
    }
}

/* ---- pass 2+3 fused: fwd FFT over h, magnitude, inverse FFT over l ------- */
__global__ __launch_bounds__(256) void k_fft_cols_absinv() {
    __shared__ float2 sb[2][4][LSTR];
    int bid = blockIdx.x, b = bid / 65, cg = bid % 65, kcb = cg << 2;
    int tid = threadIdx.x, line = tid >> 6, j = tid & 63;
#pragma unroll
    for (int k = 0; k < 8; ++k) {
        int idx = tid + 256 * k, l4 = idx & 3, i = idx >> 2;
        int kc = kcb + l4;
        float2 val = (i < 256 && kc <= 256)
                   ? g_F1[(size_t)(b * 256 + i) * F1S + kc] : make_float2(0.f, 0.f);
        sb[0][l4][padi(i)] = val;
    }
    __syncthreads();
    float2 v[8];
    load_stage(&sb[0][line][0], v, j);
    fft8<-1>(v);
    store_stage<1>(&sb[1][line][0], v, j);
    __syncthreads();
    load_stage(&sb[1][line][0], v, j);
    twiddle<-1, 8>(v, j); fft8<-1>(v);
    store_stage<8>(&sb[0][line][0], v, j);
    __syncthreads();
    load_stage(&sb[0][line][0], v, j);
    twiddle<-1, 64>(v, j); fft8<-1>(v);
    __syncthreads();
    sb[1][line][padi(j)]       = make_float2(sqrtf(v[0].x*v[0].x + v[0].y*v[0].y), 0.f);
    sb[1][line][padi(j + 64)]  = make_float2(sqrtf(v[4].x*v[4].x + v[4].y*v[4].y), 0.f);
    sb[1][line][padi(j + 128)] = make_float2(sqrtf(v[2].x*v[2].x + v[2].y*v[2].y), 0.f);
    sb[1][line][padi(j + 192)] = make_float2(sqrtf(v[6].x*v[6].x + v[6].y*v[6].y), 0.f);
    sb[1][line][padi(j + 256)] = make_float2(sqrtf(v[1].x*v[1].x + v[1].y*v[1].y), 0.f);
    sb[1][line][padi(j + 320)] = make_float2(sqrtf(v[5].x*v[5].x + v[5].y*v[5].y), 0.f);
    sb[1][line][padi(j + 384)] = make_float2(sqrtf(v[3].x*v[3].x + v[3].y*v[3].y), 0.f);
    sb[1][line][padi(j + 448)] = make_float2(sqrtf(v[7].x*v[7].x + v[7].y*v[7].y), 0.f);
    __syncthreads();
    load_stage(&sb[1][line][0], v, j);
    fft8<1>(v);
    store_stage<1>(&sb[0][line][0], v, j);
    __syncthreads();
    load_stage(&sb[0][line][0], v, j);
    twiddle<1, 8>(v, j); fft8<1>(v);
    store_stage<8>(&sb[1][line][0], v, j);
    __syncthreads();
    load_stage(&sb[1][line][0], v, j);
    twiddle<1, 64>(v, j); fft8<1>(v);
    int kr = kcb + line;
    if (kr <= 256) {
        float2* o = g_A + (size_t)(b * 257 + kr) * 512;
        o[j] = v[0]; o[j + 64] = v[4]; o[j + 128] = v[2]; o[j + 192] = v[6];
        if (j < 8) o[j + 256] = v[1];   /* pass 4 reads only h <= 263 */
    }
}

/* ---- pass 4: packed inverse FFT over k, fused fold-transpose epilogue ---- */
__global__ __launch_bounds__(256) void k_fft_cols_inv() {
    __shared__ float2 sb[2][4][LSTR];
    int bid = blockIdx.x, b = bid / 33, g = bid % 33, h0 = g << 3;
    int tid = threadIdx.x, line = tid >> 6, j = tid & 63;
#pragma unroll
    for (int it = 0; it < 8; ++it) {
        int idx = it * 256 + tid, u = idx & 3, kk = idx >> 2;
        float2 sv;
        if (kk <= 256) {
            const float4 q4 = *reinterpret_cast<const float4*>(
                g_A + (size_t)(b * 257 + kk) * 512 + h0 + 2 * u);
            sv = make_float2(q4.x - q4.w, q4.y + q4.z);
        } else {
            int k2 = 512 - kk;
            const float4 q4 = *reinterpret_cast<const float4*>(
                g_A + (size_t)(b * 257 + k2) * 512 + h0 + 2 * u);
            sv = make_float2(q4.x + q4.w, q4.z - q4.y);
        }
        sb[0][u][padi(kk)] = sv;
    }
    __syncthreads();
    float2 v[8];
    load_stage(&sb[0][line][0], v, j);
    fft8<1>(v);
    store_stage<1>(&sb[1][line][0], v, j);
    __syncthreads();
    load_stage(&sb[1][line][0], v, j);
    twiddle<1, 8>(v, j); fft8<1>(v);
    store_stage<8>(&sb[0][line][0], v, j);
    __syncthreads();
    load_stage(&sb[0][line][0], v, j);
    twiddle<1, 64>(v, j); fft8<1>(v);

    const float sc = 1.f / 262144.f;
    int ha = h0 + 2 * line, hb = ha + 1;
    float wa = ((ha != 0) && (ha != 256)) ? 2.f * sc : sc;
    float wb = 2.f * sc;   /* odd hb is never 0 or 256 */
    const int perm[8] = {0, 4, 2, 6, 1, 5, 3, 7};
#pragma unroll
    for (int r = 0; r < 8; ++r) {
        int w = j + 64 * r;
        float2 pv = v[perm[r]];
        float halfw = (w == 0) ? 0.5f : 1.f;
        if (ha <= 256)
            g_Pf[((size_t)ha * 512 + w) * 16 + b] = pv.x * (wa * halfw);
        if (hb <= 256)
            g_Pf[((size_t)hb * 512 + w) * 16 + b] = pv.y * (wb * halfw);
    }
    if (j == 0) {
        float2 pv = v[1];   /* natural position w = 256 */
        if (ha <= 256) {
            g_c256[ha * 16 + b] = pv.x * sc;
            if (ha >= 1 && ha <= 255) g_c256[(512 - ha) * 16 + b] = pv.x * sc;
        }
        if (hb <= 256) {
            g_c256[hb * 16 + b] = pv.y * sc;
            if (hb <= 255) g_c256[(512 - hb) * 16 + b] = pv.y * sc;
        }
    }
}

/* ---- mask evaluator: polynomial sin(pi r) + rational closed form --------- */
struct MaskC { float Ac, Bc, Cc, s0, l1, l2; };
__device__ __forceinline__ float mask_eval(float x, const MaskC& C) {
    float u = x * x;
    float num = fmaf(fmaf(C.Ac, u, C.Bc), u, C.Cc);
    float den = x * ((u - 1.f) * (u - 4.f));
    int ki = __float2int_rn(x);
    float r = x - (float)ki;
    float r2 = r * r;
    float sv = fmaf(fmaf(fmaf(fmaf(0.0821458866f, r2, -0.599264529f),
                              r2, 2.55016403f), r2, -5.16771278f), r2, 3.14159265f) * r;
    sv = (ki & 1) ? -sv : sv;
    float m = __fdividef(sv * num, PI_F * den);
    if (den == 0.f) {
        float ax = fabsf(x);
        m = (ax == 0.f) ? C.s0 : ((ax == 1.f) ? C.l1 : C.l2);
    }
    return m;
}

/* ---- fused mask+contraction: 4 base thetas x 8 batches per block --------- */
/* grid (23, 9, 2): z = batch half. Traffic per point conserved vs r13 (each */
/* block reads only its 32B batch slice) while accumulators drop to 32 ull   */
/* -> 2 blocks/SM (16 warps) for latency hiding.                             */
__global__ __launch_bounds__(256, 2) void k_contract(const float* __restrict__ lp) {
    const int grp = blockIdx.x, spl = blockIdx.y, bh = blockIdx.z, tid = threadIdx.x;
    const int bo = bh * 8;                       /* batch-slice float offset */
    const float lp0 = __ldg(lp), lp1 = __ldg(lp + 1), lp2 = __ldg(lp + 2);
    MaskC C;
    C.Ac = 2.f * (lp0 - lp1 + lp2);
    C.Bc = 2.f * (-5.f * lp0 + 4.f * lp1 - lp2);
    C.Cc = 8.f * lp0;
    C.s0 = 2.f * lp0; C.l1 = lp1; C.l2 = lp2;

    float ct[4], st_[4];
#pragma unroll
    for (int q = 0; q < 4; ++q) {
        float th = (float)((double)(grp * 4 + q) * 0.017453292519943295);
        ct[q] = cosf(th);
        st_[q] = sinf(th);
    }

    float accp[32], accm[32];                    /* [q*8 + bb] */

    if (spl < 8) {
        ull ap2[16], am2[16];                    /* [q*4 + lane] packed pairs */
#pragma unroll
        for (int i = 0; i < 16; ++i) { ap2[i] = 0ull; am2[i] = 0ull; }

        const int h0 = spl * 32;
#pragma unroll 1
        for (int it = 0; it < 32; ++it) {
            int idx = it * 256 + tid;
            int hi = idx >> 8, wp = idx & 255;
            float mf = (float)(h0 + hi);
            float nf = (float)wp;
            int wB = (512 - wp) & 511;

            const ulonglong2* pa = reinterpret_cast<const ulonglong2*>(
                g_Pf + (((size_t)(h0 + hi) * 512 + wp) << 4) + bo);
            const ulonglong2* pb = reinterpret_cast<const ulonglong2*>(
                g_Pf + (((size_t)(h0 + hi) * 512 + wB) << 4) + bo);
            ulonglong2 a0 = pa[0], a1 = pa[1];
            ulonglong2 b0 = pb[0], b1 = pb[1];
            ull dA[4] = {a0.x, a0.y, a1.x, a1.y};
            ull dB[4] = {b0.x, b0.y, b1.x, b1.y};

            float M[8];                          /* independent chains for ILP */
#pragma unroll
            for (int q = 0; q < 4; ++q) {
                M[2 * q]     = mask_eval(fmaf(mf, ct[q],  nf * st_[q]), C);
                M[2 * q + 1] = mask_eval(fmaf(mf, ct[q], -nf * st_[q]), C);
            }
#pragma unroll
            for (int q = 0; q < 4; ++q) {
                ull Mp2, Mm2;
                PACK2(Mp2, M[2 * q]);
                PACK2(Mm2, M[2 * q + 1]);
#pragma unroll
                for (int i = 0; i < 4; ++i) {
                    ull t;
                    int a = q * 4 + i;
                    FFMA2(t, Mm2, dB[i], ap2[a]);
                    FFMA2(ap2[a], Mp2, dA[i], t);
                    FFMA2(t, Mp2, dB[i], am2[a]);
                    FFMA2(am2[a], Mm2, dA[i], t);
                }
            }
        }
#pragma unroll
        for (int i = 0; i < 16; ++i) {
            UNPACK2(accp[2 * i], accp[2 * i + 1], ap2[i]);
            UNPACK2(accm[2 * i], accm[2 * i + 1], am2[i]);
        }
    } else {
#pragma unroll
        for (int i = 0; i < 32; ++i) { accp[i] = 0.f; accm[i] = 0.f; }
        /* (a) row h = 256, paired over w' = 0..255; this block's 8 batches */
        {
            int wp = tid;
            float mf = -256.f, nf = (float)wp;
            int wB = (512 - wp) & 511;
            const float4* pa4 = reinterpret_cast<const float4*>(
                g_Pf + (((size_t)256 * 512 + wp) << 4) + bo);
            const float4* pb4 = reinterpret_cast<const float4*>(
                g_Pf + (((size_t)256 * 512 + wB) << 4) + bo);
            float4 a0 = pa4[0], a1 = pa4[1];
            float4 b0 = pb4[0], b1 = pb4[1];
            float pA[8] = {a0.x,a0.y,a0.z,a0.w, a1.x,a1.y,a1.z,a1.w};
            float pB[8] = {b0.x,b0.y,b0.z,b0.w, b1.x,b1.y,b1.z,b1.w};
#pragma unroll
            for (int q = 0; q < 4; ++q) {
                float Mp = mask_eval(fmaf(mf, ct[q],  nf * st_[q]), C);
                float Mm = mask_eval(fmaf(mf, ct[q], -nf * st_[q]), C);
#pragma unroll
                for (int b = 0; b < 8; ++b) {
                    accp[q * 8 + b] = fmaf(Mp, pA[b], fmaf(Mm, pB[b], accp[q * 8 + b]));
                    accm[q * 8 + b] = fmaf(Mm, pA[b], fmaf(Mp, pB[b], accm[q * 8 + b]));
                }
            }
        }
        /* (b) column w = 256, all h = 0..511, exact and unpaired */
#pragma unroll 1
        for (int it = 0; it < 2; ++it) {
            int h = it * 256 + tid;
            float mf = (float)(h - ((h >= 256) ? 512 : 0));
            float nf = -256.f;
            const float4* pc4 = reinterpret_cast<const float4*>(g_c256 + h * 16 + bo);
            float4 c0 = pc4[0], c1 = pc4[1];
            float P[8] = {c0.x,c0.y,c0.z,c0.w, c1.x,c1.y,c1.z,c1.w};
#pragma unroll
            for (int q = 0; q < 4; ++q) {
                float Mp = mask_eval(fmaf( mf, ct[q], nf * st_[q]), C);   /* theta t */
                float Mm = mask_eval(fmaf(-mf, ct[q], nf * st_[q]), C);   /* theta 180-t */
#pragma unroll
                for (int b = 0; b < 8; ++b) {
                    accp[q * 8 + b] = fmaf(Mp, P[b], accp[q * 8 + b]);
                    accm[q * 8 + b] = fmaf(Mm, P[b], accm[q * 8 + b]);
                }
            }
        }
    }

    /* deterministic block reduction: warp shuffles, then one smem pass */
#pragma unroll
    for (int i = 0; i < 32; ++i) {
#pragma unroll
        for (int off = 16; off > 0; off >>= 1) {
            accp[i] += __shfl_down_sync(0xffffffffu, accp[i], off);
            accm[i] += __shfl_down_sync(0xffffffffu, accm[i], off);
        }
    }
    __shared__ float red[8][64];
    int wid = tid >> 5, lid = tid & 31;
    if (lid == 0) {
#pragma unroll
        for (int i = 0; i < 32; ++i) {
            red[wid][i] = accp[i];
            red[wid][32 + i] = accm[i];
        }
    }
    __syncthreads();
    if (tid < 64) {
        float s = 0.f;
#pragma unroll
        for (int w8 = 0; w8 < 8; ++w8) s += red[w8][tid];
        g_part[(((size_t)grp * 9 + spl) * 2 + bh) * 64 + tid] = s;
    }
}

/* ---- final reduction: slot map (grp,q,sign,bh) -> (t,b), fold 1/(H*W) ---- */
__global__ __launch_bounds__(256) void k_reduce(float* __restrict__ out) {
    int i = blockIdx.x * 256 + threadIdx.x;
    if (i >= 2880) return;
    int t = i % 180, b = i / 180;
    int bt, sign;
    if (t <= 90) { bt = t; sign = 0; }
    else         { bt = 180 - t; sign = 1; }
    int grp = bt >> 2, q = bt & 3;
    int bh = b >> 3, bb = b & 7;
    int off = sign * 32 + q * 8 + bb;
    float s = 0.f;
#pragma unroll
    for (int spl = 0; spl < 9; ++spl)
        s += g_part[(((size_t)grp * 9 + spl) * 2 + bh) * 64 + off];
    out[b * 180 + t] = s * (1.f / 262144.f);
}

/* -------------------------------------------------------------------------- */
extern "C" void kernel_launch(void* const* d_in, const int* in_sizes, int n_in,
                              void* d_out, int out_size) {
    const float* batch = (const float*)d_in[0];   /* [16,256,256] */
    const float* lp    = (const float*)d_in[1];   /* [3]          */
    float* out         = (float*)d_out;           /* [16,180]     */
    (void)in_sizes; (void)n_in; (void)out_size;

    k_fft_rows_fwd<<<512, 256>>>(batch);
    k_fft_cols_absinv<<<1040, 256>>>();
    k_fft_cols_inv<<<528, 256>>>();
    k_contract<<<dim3(23, 9, 2), 256>>>(lp);
    k_reduce<<<12, 256>>>(out);
}